// round 9
// baseline (speedup 1.0000x reference)
#include <cuda_runtime.h>
#include <cuda_bf16.h>
#include <cstdint>

// ---------------- problem constants ----------------
#define BB 8
#define DD 64
#define TT 8192
#define KK 1024
#define NROWS 65536
#define NZ 4194304
#define THREADS 128
#define MROWS 64              // rows per CTA (one m16 tile per warp)
#define NBLOCKS 1024
#define NC 32                 // codes per chunk
#define NCHUNKS 32

// ---------------- device scratch (no allocs allowed) ----------------
__device__ float g_wnorm[KK];
__device__ float g_partial[NBLOCKS];
__device__ unsigned int g_ticket;     // zero-init; reset by last block every run
__device__ __align__(16) __nv_bfloat16 g_wh[KK * DD];   // fragment-permuted rows
__device__ __align__(16) __nv_bfloat16 g_wl[KK * DD];

// ---------------- static SMEM layout (23296 B; regs bind occupancy at 7/SM) ----------------
#define B_ROW_STRIDE 144              // 128B data + 16B pad -> conflict-free LDS.128
#define B_PART (NC * B_ROW_STRIDE)    // 4608 B per (chunk, hi/lo part)
#define B_BUF  (2 * B_PART)           // 9216 B per buffer (hi+lo)
#define SM_B    0                     // 2 buffers: 18432 B (also reused for z staging: 64*65*4=16640)
#define SM_WN   18432                 // wnorm[1024] fp32: 4096 B
#define SM_ZN   22528                 // znorm[64]: 256 B
#define SM_RED  22784                 // loss reduction[128]: 512 B
#define SM_SIZE 23296

// ---------------- helpers ----------------
__device__ __forceinline__ uint32_t smem_u32(const void* p) {
    uint32_t a;
    asm("{ .reg .u64 t; cvta.to.shared.u64 t, %1; cvt.u32.u64 %0, t; }" : "=r"(a) : "l"(p));
    return a;
}
__device__ __forceinline__ void cp_async16(uint32_t dst, const void* src) {
    asm volatile("cp.async.cg.shared.global [%0], [%1], 16;" :: "r"(dst), "l"(src));
}
#define CP_COMMIT()  asm volatile("cp.async.commit_group;" ::: "memory")
#define CP_WAIT(n)   asm volatile("cp.async.wait_group %0;" :: "n"(n) : "memory")

// packed f32x2 (sm_103 packed fp32 pipe)
__device__ __forceinline__ unsigned long long pk2(float lo, float hi) {
    unsigned long long r;
    asm("mov.b64 %0, {%1, %2};" : "=l"(r) : "f"(lo), "f"(hi));
    return r;
}
__device__ __forceinline__ void unpk2(unsigned long long v, float& lo, float& hi) {
    asm("mov.b64 {%0, %1}, %2;" : "=f"(lo), "=f"(hi) : "l"(v));
}
__device__ __forceinline__ unsigned long long fma2(unsigned long long a, unsigned long long b, unsigned long long c) {
    unsigned long long d;
    asm("fma.rn.f32x2 %0, %1, %2, %3;" : "=l"(d) : "l"(a), "l"(b), "l"(c));
    return d;
}
__device__ __forceinline__ unsigned long long add2(unsigned long long a, unsigned long long b) {
    unsigned long long d;
    asm("add.rn.f32x2 %0, %1, %2;" : "=l"(d) : "l"(a), "l"(b));
    return d;
}

// m16n8k16 bf16 MMA, fp32 accumulate
#define MMA_BF16(acc, a, b) \
    asm volatile("mma.sync.aligned.m16n8k16.row.col.f32.bf16.bf16.f32 " \
        "{%0,%1,%2,%3},{%4,%5,%6,%7},{%8,%9},{%0,%1,%2,%3};" \
        : "+f"((acc)[0]), "+f"((acc)[1]), "+f"((acc)[2]), "+f"((acc)[3]) \
        : "r"((a)[0]), "r"((a)[1]), "r"((a)[2]), "r"((a)[3]), \
          "r"((b)[0]), "r"((b)[1]))

__device__ __forceinline__ void split2(float a, float b, uint32_t& h, uint32_t& lo) {
    __nv_bfloat16 ha = __float2bfloat16(a), hb = __float2bfloat16(b);
    float ra = __fsub_rn(a, __bfloat162float(ha));
    float rb = __fsub_rn(b, __bfloat162float(hb));
    __nv_bfloat16 la = __float2bfloat16(ra), lb = __float2bfloat16(rb);
    h  = (uint32_t)__bfloat16_as_ushort(ha) | ((uint32_t)__bfloat16_as_ushort(hb) << 16);
    lo = (uint32_t)__bfloat16_as_ushort(la) | ((uint32_t)__bfloat16_as_ushort(lb) << 16);
}

// fragment permutation: element kk (0..63) of a W row -> bf16 slot
// kk = kt*16 + half*8 + 2*t + e  ->  idx = t*16 + kt*4 + half*2 + e
__device__ __host__ __forceinline__ int permidx(int kk) {
    int kt = kk >> 4, r = kk & 15;
    int half = r >> 3, s = r & 7, tq = s >> 1, e = s & 1;
    return tq * 16 + kt * 4 + half * 2 + e;
}

// ---------------- prep: wnorm (R1-identical rounding order) + permuted bf16 split ----------------
__global__ void vq_prep_kernel(const float* __restrict__ W) {
    int k = blockIdx.x * blockDim.x + threadIdx.x;
    if (k >= KK) return;
    const float4* wr = reinterpret_cast<const float4*>(W + (size_t)k * DD);
    float t32[32];
    uint32_t uh[32], ul[32];
#pragma unroll
    for (int i = 0; i < 32; i++) { uh[i] = 0; ul[i] = 0; }
#pragma unroll
    for (int j = 0; j < 8; j++) {
        float4 va = wr[j];
        float4 vb = wr[j + 8];
        float av[4] = {va.x, va.y, va.z, va.w};
        float bv[4] = {vb.x, vb.y, vb.z, vb.w};
#pragma unroll
        for (int q = 0; q < 4; q++) {
            t32[4 * j + q] = __fadd_rn(__fmul_rn(av[q], av[q]), __fmul_rn(bv[q], bv[q]));
            {
                int idx = permidx(4 * j + q);
                __nv_bfloat16 h = __float2bfloat16(av[q]);
                __nv_bfloat16 l = __float2bfloat16(__fsub_rn(av[q], __bfloat162float(h)));
                uh[idx >> 1] |= (uint32_t)__bfloat16_as_ushort(h) << (16 * (idx & 1));
                ul[idx >> 1] |= (uint32_t)__bfloat16_as_ushort(l) << (16 * (idx & 1));
            }
            {
                int idx = permidx(4 * j + q + 32);
                __nv_bfloat16 h = __float2bfloat16(bv[q]);
                __nv_bfloat16 l = __float2bfloat16(__fsub_rn(bv[q], __bfloat162float(h)));
                uh[idx >> 1] |= (uint32_t)__bfloat16_as_ushort(h) << (16 * (idx & 1));
                ul[idx >> 1] |= (uint32_t)__bfloat16_as_ushort(l) << (16 * (idx & 1));
            }
        }
    }
#pragma unroll
    for (int off = 16; off >= 1; off >>= 1) {
#pragma unroll
        for (int j = 0; j < 16; j++) {
            if (j < off) t32[j] = __fadd_rn(t32[j], t32[j + off]);
        }
    }
    g_wnorm[k] = t32[0];
    uint4* dh = reinterpret_cast<uint4*>(g_wh + (size_t)k * DD);
    uint4* dl = reinterpret_cast<uint4*>(g_wl + (size_t)k * DD);
#pragma unroll
    for (int i = 0; i < 8; i++) {
        dh[i] = make_uint4(uh[4 * i], uh[4 * i + 1], uh[4 * i + 2], uh[4 * i + 3]);
        dl[i] = make_uint4(ul[4 * i], ul[4 * i + 1], ul[4 * i + 2], ul[4 * i + 3]);
    }
}

// ---------------- chunk prefetch via cp.async (NC=32: 256 x 16B per part) ----------------
__device__ __forceinline__ void issue_chunk(uint32_t sb, int chunk, int buf, int tid) {
    const uint4* srcH = reinterpret_cast<const uint4*>(g_wh + (size_t)chunk * NC * DD);
    const uint4* srcL = reinterpret_cast<const uint4*>(g_wl + (size_t)chunk * NC * DD);
    uint32_t dH = sb + SM_B + buf * B_BUF;
    uint32_t dL = dH + B_PART;
#pragma unroll
    for (int i = 0; i < 2; i++) {
        int idx = tid + i * THREADS;          // 0..255: row = idx/8, 16B col = idx%8
        uint32_t off = (uint32_t)(idx >> 3) * B_ROW_STRIDE + (uint32_t)(idx & 7) * 16;
        cp_async16(dH + off, srcH + idx);
        cp_async16(dL + off, srcL + idx);
    }
}

// ---------------- per-chunk: 12 HMMA x 4nt + packed dist + argmin (mt=1) ----------------
__device__ __forceinline__ void process_chunk(
    const char* smp, int c, int g, int t,
    const uint32_t ah[4][4], const uint32_t al[4][4],
    unsigned long long zpkA, unsigned long long zpkB,
    unsigned long long NEG2, float dmin[2], int imin[2])
{
    const char* bbase = smp + SM_B + (c & 1) * B_BUF;
#pragma unroll
    for (int nt = 0; nt < 4; nt++) {
        const char* rowp = bbase + (nt * 8 + g) * B_ROW_STRIDE + t * 32;
        uint4 h0 = *reinterpret_cast<const uint4*>(rowp);
        uint4 h1 = *reinterpret_cast<const uint4*>(rowp + 16);
        uint4 l0 = *reinterpret_cast<const uint4*>(rowp + B_PART);
        uint4 l1 = *reinterpret_cast<const uint4*>(rowp + B_PART + 16);
        uint32_t bh[4][2] = {{h0.x, h0.y}, {h0.z, h0.w}, {h1.x, h1.y}, {h1.z, h1.w}};
        uint32_t bl[4][2] = {{l0.x, l0.y}, {l0.z, l0.w}, {l1.x, l1.y}, {l1.z, l1.w}};
        float acc[4] = {0.f, 0.f, 0.f, 0.f};
#pragma unroll
        for (int kt = 0; kt < 4; kt++) MMA_BF16(acc, ah[kt], bh[kt]);  // hh
#pragma unroll
        for (int kt = 0; kt < 4; kt++) MMA_BF16(acc, ah[kt], bl[kt]);  // hl
#pragma unroll
        for (int kt = 0; kt < 4; kt++) MMA_BF16(acc, al[kt], bh[kt]);  // lh

        const int cb = c * NC + nt * 8 + 2 * t;
        unsigned long long wpk = *reinterpret_cast<const unsigned long long*>(smp + SM_WN + (size_t)cb * 4);
        // per lane: fadd(fma(s, -2, znorm), wn) == fadd(fsub(znorm, 2s), wn) bitwise (2s exact)
        unsigned long long dA = add2(fma2(pk2(acc[0], acc[1]), NEG2, zpkA), wpk);
        unsigned long long dB = add2(fma2(pk2(acc[2], acc[3]), NEG2, zpkB), wpk);
        float d0, d1, d2, d3;
        unpk2(dA, d0, d1);
        unpk2(dB, d2, d3);
        if (d0 < dmin[0]) { dmin[0] = d0; imin[0] = cb; }
        if (d1 < dmin[0]) { dmin[0] = d1; imin[0] = cb + 1; }
        if (d2 < dmin[1]) { dmin[1] = d2; imin[1] = cb; }
        if (d3 < dmin[1]) { dmin[1] = d3; imin[1] = cb + 1; }
    }
}

// ---------------- main kernel (finalize fused via last-block ticket) ----------------
__global__ __launch_bounds__(THREADS, 7)
void vq_main_kernel(const float* __restrict__ z,
                    const float* __restrict__ W,
                    float* __restrict__ out_zq,
                    float* __restrict__ out_codes,
                    float* __restrict__ out_loss) {
    __shared__ __align__(16) char smp[SM_SIZE];
    const uint32_t sb = smem_u32(smp);

    const int tid = threadIdx.x;
    const int w = tid >> 5;
    const int l = tid & 31;
    const int g = l >> 2;
    const int t = l & 3;

    // ---- stage z rows (2 threads/row) + znorm (R1-identical rounding order) ----
    {
        const int row = tid >> 1;                  // 0..63
        const int half = tid & 1;                  // cols half*32 .. +31
        const int grow = blockIdx.x * MROWS + row;
        const float* zp = z + (size_t)(grow >> 13) * DD * TT + (grow & (TT - 1));
        float* zr = reinterpret_cast<float*>(smp) + row * 65 + half * 32;
        float sq[16];
#pragma unroll
        for (int j = 0; j < 16; j++) {
            float v0 = zp[(size_t)(half * 32 + 2 * j) * TT];
            float v1 = zp[(size_t)(half * 32 + 2 * j + 1) * TT];
            zr[2 * j] = v0;
            zr[2 * j + 1] = v1;
            sq[j] = __fadd_rn(__fmul_rn(v0, v0), __fmul_rn(v1, v1));
        }
        // R1 tree level off=16: sq[j](cols 0..31) + sq[j+16](cols 32..63): half0 + half1
#pragma unroll
        for (int j = 0; j < 16; j++) {
            float other = __shfl_xor_sync(0xffffffff, sq[j], 1);
            sq[j] = half ? __fadd_rn(other, sq[j]) : __fadd_rn(sq[j], other);
        }
#pragma unroll
        for (int off = 8; off >= 1; off >>= 1) {
#pragma unroll
            for (int j = 0; j < 8; j++) {
                if (j < off) sq[j] = __fadd_rn(sq[j], sq[j + off]);
            }
        }
        if (half == 0) reinterpret_cast<float*>(smp + SM_ZN)[row] = sq[0];
    }
    __syncthreads();

    // ---- register-resident A fragments (zh, zl), one m16 tile per warp ----
    uint32_t ah[4][4], al[4][4];
    {
        const float* r0 = reinterpret_cast<const float*>(smp) + (w * 16 + g) * 65;
        const float* r1 = r0 + 8 * 65;
#pragma unroll
        for (int kt = 0; kt < 4; kt++) {
            const int c0 = kt * 16 + 2 * t;
            split2(r0[c0],     r0[c0 + 1], ah[kt][0], al[kt][0]);
            split2(r1[c0],     r1[c0 + 1], ah[kt][1], al[kt][1]);
            split2(r0[c0 + 8], r0[c0 + 9], ah[kt][2], al[kt][2]);
            split2(r1[c0 + 8], r1[c0 + 9], ah[kt][3], al[kt][3]);
        }
    }
    unsigned long long zpkA, zpkB;
    {
        float a = reinterpret_cast<const float*>(smp + SM_ZN)[w * 16 + g];
        float b = reinterpret_cast<const float*>(smp + SM_ZN)[w * 16 + g + 8];
        zpkA = pk2(a, a);
        zpkB = pk2(b, b);
    }
    const unsigned long long NEG2 = pk2(-2.0f, -2.0f);
    __syncthreads();   // z staging region now free -> becomes B buffers

    // ---- prefetch chunk 0; load wnorm table ----
    issue_chunk(sb, 0, 0, tid); CP_COMMIT();
    {
        float* sWN = reinterpret_cast<float*>(smp + SM_WN);
#pragma unroll
        for (int i = 0; i < KK / THREADS; i++)
            sWN[tid + i * THREADS] = g_wnorm[tid + i * THREADS];
    }

    float dmin[2] = {3.4e38f, 3.4e38f};
    int imin[2] = {0, 0};

    // ---- pipeline: ONE barrier per chunk, 2 buffers, prefetch distance 1 ----
    for (int c = 0; c < NCHUNKS; c++) {
        CP_WAIT(0);
        __syncthreads();
        if (c + 1 < NCHUNKS) { issue_chunk(sb, c + 1, (c + 1) & 1, tid); CP_COMMIT(); }
        process_chunk(smp, c, g, t, ah, al, zpkA, zpkB, NEG2, dmin, imin);
    }

    // ---- cross-lane reduce over the t-quad (smaller index wins ties) ----
#pragma unroll
    for (int s = 0; s < 2; s++) {
#pragma unroll
        for (int o = 1; o < 4; o <<= 1) {
            float od = __shfl_xor_sync(0xffffffff, dmin[s], o);
            int   oi = __shfl_xor_sync(0xffffffff, imin[s], o);
            if (od < dmin[s] || (od == dmin[s] && oi < imin[s])) { dmin[s] = od; imin[s] = oi; }
        }
    }
    // thread role: row-half h = t&1, column half = t>>1
    const int h = t & 1;
    const int my = h ? imin[1] : imin[0];

    // ---- outputs: codes, z_q_st = z + (w - z), loss partial ----
    const int rown = w * 16 + g + 8 * h;
    const int grow = blockIdx.x * MROWS + rown;
    if (t < 2) out_codes[grow] = (float)my;      // t=0 -> row g, t=1 -> row g+8

    const int b = grow >> 13;
    const int tp = grow & (TT - 1);
    const int cbase = (t >> 1) * 32;             // this thread covers 32 dims
    const float* zp = z + (size_t)b * DD * TT + tp;
    float* oz = out_zq + (size_t)b * DD * TT + tp;
    const float4* wrow = reinterpret_cast<const float4*>(W + (size_t)my * DD + cbase);
    float lsum = 0.0f;
#pragma unroll
    for (int j = 0; j < 8; j++) {
        float4 wv = wrow[j];
        float wa[4] = {wv.x, wv.y, wv.z, wv.w};
#pragma unroll
        for (int q = 0; q < 4; q++) {
            const int d = cbase + 4 * j + q;
            float zv = zp[(size_t)d * TT];
            float e = __fsub_rn(wa[q], zv);
            oz[(size_t)d * TT] = __fadd_rn(zv, e);   // straight-through estimator
            lsum = __fadd_rn(lsum, __fmul_rn(e, e));
        }
    }

    float* sRed = reinterpret_cast<float*>(smp + SM_RED);
    sRed[tid] = lsum;
    __syncthreads();
#pragma unroll
    for (int s = THREADS / 2; s > 0; s >>= 1) {
        if (tid < s) sRed[tid] += sRed[tid + s];
        __syncthreads();
    }

    // ---- fused finalize: last block reduces all 1024 partials (deterministic order) ----
    __shared__ unsigned int sIsLast;
    if (tid == 0) {
        g_partial[blockIdx.x] = sRed[0];
        __threadfence();
        unsigned int tk = atomicAdd(&g_ticket, 1u);
        sIsLast = (tk == NBLOCKS - 1) ? 1u : 0u;
    }
    __syncthreads();
    if (sIsLast) {
        float v = 0.0f;
#pragma unroll
        for (int i = 0; i < NBLOCKS / THREADS; i++)
            v = __fadd_rn(v, g_partial[tid + i * THREADS]);
        sRed[tid] = v;
        __syncthreads();
#pragma unroll
        for (int s = THREADS / 2; s > 0; s >>= 1) {
            if (tid < s) sRed[tid] += sRed[tid + s];
            __syncthreads();
        }
        if (tid == 0) {
            out_loss[0] = 1.25f * (sRed[0] / (float)NZ);
            g_ticket = 0;    // reset for next graph replay
        }
    }
}

extern "C" void kernel_launch(void* const* d_in, const int* in_sizes, int n_in,
                              void* d_out, int out_size) {
    const float* z = (const float*)d_in[0];      // [8, 64, 8192]
    const float* W = (const float*)d_in[1];      // [1024, 64]
    float* out = (float*)d_out;
    float* out_zq    = out;
    float* out_loss  = out + NZ;
    float* out_codes = out + NZ + 1;

    vq_prep_kernel<<<32, 32>>>(W);
    vq_main_kernel<<<NBLOCKS, THREADS>>>(z, W, out_zq, out_codes, out_loss);
}